// round 14
// baseline (speedup 1.0000x reference)
#include <cuda_runtime.h>
#include <cstdint>

// out[s, r, j] = in[r, idx[s] + j]
// in: (131072, 512) fp32 ; idx: (16,) int32 in [0,448) ; out: (16, 131072, 64) fp32
//
// FINAL — reproduced 4x at kernel 116.0-116.4us (sigma ~0.15us), harness
// 117.9-118.8us. Design space fully mapped (R4-R13):
//   RPC=2: 119.6us k | RPC=4: 116.1us k (this) | RPC=8: 115.8us k, worse harness
//   __ldcs/__stcs: neutral
//   persistent + double-buffer: 127.4us k (barrier exposes staging latency;
//     cross-CTA phase overlap from independent short CTAs is strictly better)
//   direct gather, no smem: 125.5us k (scalar misaligned LDGs -> L1tex
//     wavefront-bound; smem staging IS the coalescing engine)
//
// Structure: 4 rows/CTA staged in smem via 2 front-batched coalesced
// LDG.128/thread, predicated on slice coverage (sector-exact: ~8% of row
// bytes never fetched). Emit: thread t -> slice s=t>>4, quad v=(t&15)*4,
// one STG.128 per row; warps stream contiguous 256B full-sector segments.
// Roofline: 512MB write + ~220MB read = ~730MB at 6.3TB/s achieved
// (79.4% DRAM = this part's mixed-R/W controller ceiling) = 115.9us;
// measured 116.1us. The kernel sits on its roofline.

#define FEAT 512
#define NUM_SLICES 16
#define SLICE_LEN 64
#define RPC 4   // rows per CTA (n_rows % RPC == 0 for this problem)

__global__ __launch_bounds__(256) void fuse_slice_kernel(
    const float* __restrict__ in,
    const int* __restrict__ idx,
    float* __restrict__ out,
    int n_rows)
{
    __shared__ float row[RPC][FEAT];
    __shared__ int sidx[NUM_SLICES];

    const int t = threadIdx.x;
    const size_t r0 = (size_t)blockIdx.x * RPC;

    if (t < NUM_SLICES) sidx[t] = idx[t];
    __syncthreads();

    // ---- staging: 512 float4 chunks per CTA, 2 per thread.
    // chunk c = t + 256*i -> row k = (t>>7) + 2*i, float4-index c4 = t&127.
    // Coverage predicate depends only on c4 -> computed once per thread.
    // Chunk [col, col+3] intersects slice [b, b+63] iff col-b in [-3, 63].
    const int c4  = t & 127;
    const int col = c4 << 2;

    bool need = false;
    #pragma unroll
    for (int s = 0; s < NUM_SLICES; s++) {
        const int d = col - sidx[s];
        need |= ((unsigned)(d + 3) < (unsigned)(SLICE_LEN + 3));
    }

    const int k0 = t >> 7;  // 0 or 1; second chunk is row k0+2
    if (need) {
        #pragma unroll
        for (int i = 0; i < 2; i++) {
            const int k = k0 + 2 * i;
            reinterpret_cast<float4*>(row[k])[c4] =
                reinterpret_cast<const float4*>(in + (r0 + k) * FEAT)[c4];
        }
    }
    __syncthreads();

    // ---- emit: thread t -> slice s, quad v; one float4 store per row.
    const int s = t >> 4;
    const int v = (t & 15) << 2;
    const int base = sidx[s] + v;

    #pragma unroll
    for (int k = 0; k < RPC; k++) {
        float4 val;
        val.x = row[k][base + 0];
        val.y = row[k][base + 1];
        val.z = row[k][base + 2];
        val.w = row[k][base + 3];

        const size_t o = (((size_t)s * n_rows + (r0 + k)) << 6) + (size_t)v;
        *reinterpret_cast<float4*>(out + o) = val;
    }
}

extern "C" void kernel_launch(void* const* d_in, const int* in_sizes, int n_in,
                              void* d_out, int out_size)
{
    const float* in  = (const float*)d_in[0];
    const int*   idx = (const int*)d_in[1];
    float*       out = (float*)d_out;

    const int n_rows = in_sizes[0] / FEAT;   // 131072, multiple of RPC

    fuse_slice_kernel<<<n_rows / RPC, 256>>>(in, idx, out, n_rows);
}

// round 15
// speedup vs baseline: 1.0177x; 1.0177x over previous
#include <cuda_runtime.h>
#include <cstdint>

// out[s, r, j] = in[r, idx[s] + j]
// in: (131072, 512) fp32 ; idx: (16,) int32 in [0,448) ; out: (16, 131072, 64) fp32
//
// FINAL — reproduced 5x: kernel 116.0-117.0us (drift ~1us), harness
// 117.9-119.5us. Design space fully mapped (R4-R14):
//   RPC=2: 119.6us k | RPC=4: 116.3us k mean (this) | RPC=8: 115.8us k
//     (single sample, inside drift band; worse harness)
//   __ldcs/__stcs: neutral
//   persistent + double-buffer: 127.4us k (barrier exposes staging latency;
//     cross-CTA phase overlap from independent short CTAs is strictly better)
//   direct gather, no smem: 125.5us k (scalar misaligned LDGs -> L1tex
//     wavefront-bound; smem staging IS the coalescing engine)
//
// Structure: 4 rows/CTA staged in smem via 2 front-batched coalesced
// LDG.128/thread, predicated on slice coverage (sector-exact at the 32B
// sector grain; ~8% of row bytes never fetched). Emit: thread t -> slice
// s=t>>4, quad v=(t&15)*4, one STG.128 per row; warps stream contiguous
// 256B full-sector segments (no RFO).
// Roofline: 512MB write + ~220MB read = ~730MB at 6.25-6.33TB/s achieved
// (79% DRAM = this part's mixed-R/W controller ceiling) = 115.5-116.8us;
// measured 116.0-117.0us. The kernel sits on its roofline.

#define FEAT 512
#define NUM_SLICES 16
#define SLICE_LEN 64
#define RPC 4   // rows per CTA (n_rows % RPC == 0 for this problem)

__global__ __launch_bounds__(256) void fuse_slice_kernel(
    const float* __restrict__ in,
    const int* __restrict__ idx,
    float* __restrict__ out,
    int n_rows)
{
    __shared__ float row[RPC][FEAT];
    __shared__ int sidx[NUM_SLICES];

    const int t = threadIdx.x;
    const size_t r0 = (size_t)blockIdx.x * RPC;

    if (t < NUM_SLICES) sidx[t] = idx[t];
    __syncthreads();

    // ---- staging: 512 float4 chunks per CTA, 2 per thread.
    // chunk c = t + 256*i -> row k = (t>>7) + 2*i, float4-index c4 = t&127.
    // Coverage predicate depends only on c4 -> computed once per thread.
    // Chunk [col, col+3] intersects slice [b, b+63] iff col-b in [-3, 63].
    const int c4  = t & 127;
    const int col = c4 << 2;

    bool need = false;
    #pragma unroll
    for (int s = 0; s < NUM_SLICES; s++) {
        const int d = col - sidx[s];
        need |= ((unsigned)(d + 3) < (unsigned)(SLICE_LEN + 3));
    }

    const int k0 = t >> 7;  // 0 or 1; second chunk is row k0+2
    if (need) {
        #pragma unroll
        for (int i = 0; i < 2; i++) {
            const int k = k0 + 2 * i;
            reinterpret_cast<float4*>(row[k])[c4] =
                reinterpret_cast<const float4*>(in + (r0 + k) * FEAT)[c4];
        }
    }
    __syncthreads();

    // ---- emit: thread t -> slice s, quad v; one float4 store per row.
    const int s = t >> 4;
    const int v = (t & 15) << 2;
    const int base = sidx[s] + v;

    #pragma unroll
    for (int k = 0; k < RPC; k++) {
        float4 val;
        val.x = row[k][base + 0];
        val.y = row[k][base + 1];
        val.z = row[k][base + 2];
        val.w = row[k][base + 3];

        const size_t o = (((size_t)s * n_rows + (r0 + k)) << 6) + (size_t)v;
        *reinterpret_cast<float4*>(out + o) = val;
    }
}

extern "C" void kernel_launch(void* const* d_in, const int* in_sizes, int n_in,
                              void* d_out, int out_size)
{
    const float* in  = (const float*)d_in[0];
    const int*   idx = (const int*)d_in[1];
    float*       out = (float*)d_out;

    const int n_rows = in_sizes[0] / FEAT;   // 131072, multiple of RPC

    fuse_slice_kernel<<<n_rows / RPC, 256>>>(in, idx, out, n_rows);
}